// round 9
// baseline (speedup 1.0000x reference)
#include <cuda_runtime.h>
#include <math.h>

// WeightedGaussianPool: O[i,b] = sum_j cos(pi/2*d_ij)*step(1-d_ij)*f_j
//                                      * exp(-beta*(d_ij-means[b])^2)
// N=2048, B=64, beta=4096, means=linspace(0,1,64).
//
// R9 = R8 consumer (single predicate-routed EX2 per pair, x4-unrolled
// LDS.128 list walk) + 2-rows-per-block producer sharing:
//  - block (256 thr, 8 warps) owns rows i0=2b, i1=2b+1.
//  - per 64-wide j-chunk visit, a warp loads each j's coords+f ONCE and
//    produces pairs for BOTH rows -> 8 LDG per visit instead of 16,
//    loop/compaction overhead per covered pair halved.
//  - ping-pong pair lists: one __syncwarp per visit.
//  - block smem reduction, plain STG (no atomics).

#define CUTOFF   5.0f
#define PI_HALF  1.5707963267948966f
#define NBASIS   64
#define WPB      8

__device__ __forceinline__ float ex2_fast(float x) {
    float r;
    asm("ex2.approx.ftz.f32 %0, %1;" : "=f"(r) : "f"(x));
    return r;
}
__device__ __forceinline__ float sqrt_fast(float x) {
    float r;
    asm("sqrt.approx.ftz.f32 %0, %1;" : "=f"(r) : "f"(x));
    return r;
}

__global__ __launch_bounds__(WPB * 32, 8)
void wgp_main_kernel(const float* __restrict__ f,
                     const float* __restrict__ coords,
                     const float* __restrict__ means,
                     const float* __restrict__ beta_p,
                     float* __restrict__ out,
                     int N) {
    // [warp][pingpong][row][64 pairs + 3 pad + align]
    __shared__ __align__(16) float2 buf[WPB][2][2][68];
    __shared__ float red[WPB][2][NBASIS];

    const int lane = threadIdx.x & 31;
    const int wrp  = threadIdx.x >> 5;
    const int i0   = 2 * blockIdx.x;
    const int i1   = i0 + 1;

    const float beta = *beta_p;
    const float a    = sqrtf(beta * 1.4426950408889634f); // sqrt(beta*log2 e)
    const float aC   = a / CUTOFF;
    const float pC   = PI_HALF / CUTOFF;
    const float C2   = CUTOFF * CUTOFF;
    const float am1  = a * means[lane];
    const float am2  = a * means[lane + 32];
    const float D    = am2 - am1;
    const float midp = 0.5f * (am1 + am2);

    const float x0 = coords[3 * i0 + 0], y0 = coords[3 * i0 + 1], z0 = coords[3 * i0 + 2];
    const float x1 = coords[3 * i1 + 0], y1 = coords[3 * i1 + 1], z1 = coords[3 * i1 + 2];

    float acc01 = 0.0f, acc02 = 0.0f;   // row i0: bases [0,32)/[32,64)
    float acc11 = 0.0f, acc12 = 0.0f;   // row i1
    int pb = 0;

    const unsigned below = (1u << lane) - 1u;
    const int nch64 = N >> 6;

    for (int c = wrp; c < nch64; c += WPB) {
        const int ja = (c << 6) + lane;
        const int jb = ja + 32;

        // ---- shared loads for half A ----
        const float cxa = coords[3 * ja + 0];
        const float cya = coords[3 * ja + 1];
        const float cza = coords[3 * ja + 2];
        const float fa  = f[ja];
        // ---- shared loads for half B ----
        const float cxb = coords[3 * jb + 0];
        const float cyb = coords[3 * jb + 1];
        const float czb = coords[3 * jb + 2];
        const float fb  = f[jb];

        // distances: 2 rows x 2 halves
        float dp0a = 0.f, w0a = 0.f, dp0b = 0.f, w0b = 0.f;
        float dp1a = 0.f, w1a = 0.f, dp1b = 0.f, w1b = 0.f;
        bool a0a, a0b, a1a, a1b;
        {
            const float dx = x0 - cxa, dy = y0 - cya, dz = z0 - cza;
            const float sq = fmaf(dx, dx, fmaf(dy, dy, dz * dz));
            a0a = (sq <= C2);
            if (a0a) { const float dr = sqrt_fast(sq); dp0a = aC * dr; w0a = __cosf(pC * dr) * fa; }
        }
        {
            const float dx = x0 - cxb, dy = y0 - cyb, dz = z0 - czb;
            const float sq = fmaf(dx, dx, fmaf(dy, dy, dz * dz));
            a0b = (sq <= C2);
            if (a0b) { const float dr = sqrt_fast(sq); dp0b = aC * dr; w0b = __cosf(pC * dr) * fb; }
        }
        {
            const float dx = x1 - cxa, dy = y1 - cya, dz = z1 - cza;
            const float sq = fmaf(dx, dx, fmaf(dy, dy, dz * dz));
            a1a = (sq <= C2);
            if (a1a) { const float dr = sqrt_fast(sq); dp1a = aC * dr; w1a = __cosf(pC * dr) * fa; }
        }
        {
            const float dx = x1 - cxb, dy = y1 - cyb, dz = z1 - czb;
            const float sq = fmaf(dx, dx, fmaf(dy, dy, dz * dz));
            a1b = (sq <= C2);
            if (a1b) { const float dr = sqrt_fast(sq); dp1b = aC * dr; w1b = __cosf(pC * dr) * fb; }
        }

        const unsigned b0a = __ballot_sync(0xffffffffu, a0a);
        const unsigned b0b = __ballot_sync(0xffffffffu, a0b);
        const unsigned b1a = __ballot_sync(0xffffffffu, a1a);
        const unsigned b1b = __ballot_sync(0xffffffffu, a1b);
        const int n0a = __popc(b0a);
        const int n1a = __popc(b1a);
        const int n0  = n0a + __popc(b0b);
        const int n1  = n1a + __popc(b1b);
        if ((n0 | n1) == 0) continue;

        float2* bp0 = buf[wrp][pb][0];
        float2* bp1 = buf[wrp][pb][1];
        if (a0a) bp0[__popc(b0a & below)]       = make_float2(dp0a, w0a);
        if (a0b) bp0[n0a + __popc(b0b & below)] = make_float2(dp0b, w0b);
        if (a1a) bp1[__popc(b1a & below)]       = make_float2(dp1a, w1a);
        if (a1b) bp1[n1a + __popc(b1b & below)] = make_float2(dp1b, w1b);
        if (lane < 3) {
            bp0[n0 + lane] = make_float2(1.0e4f, 0.0f);
            bp1[n1 + lane] = make_float2(1.0e4f, 0.0f);
        }
        __syncwarp();

#define PAIR(dq, wq, A1, A2)                                      \
        {                                                         \
            const float t1 = (dq) - am1;                          \
            const bool  lo = (dq) < midp;                         \
            const float t  = lo ? t1 : (t1 - D);                  \
            const float e  = ex2_fast(-t * t);                    \
            if (lo) A1 = fmaf((wq), e, A1);                       \
            else    A2 = fmaf((wq), e, A2);                       \
        }

        const int n04 = (n0 + 3) & ~3;
        for (int k = 0; k < n04; k += 4) {
            const float4 q0 = *(const float4*)&bp0[k];
            const float4 q1 = *(const float4*)&bp0[k + 2];
            PAIR(q0.x, q0.y, acc01, acc02)
            PAIR(q0.z, q0.w, acc01, acc02)
            PAIR(q1.x, q1.y, acc01, acc02)
            PAIR(q1.z, q1.w, acc01, acc02)
        }
        const int n14 = (n1 + 3) & ~3;
        for (int k = 0; k < n14; k += 4) {
            const float4 q0 = *(const float4*)&bp1[k];
            const float4 q1 = *(const float4*)&bp1[k + 2];
            PAIR(q0.x, q0.y, acc11, acc12)
            PAIR(q0.z, q0.w, acc11, acc12)
            PAIR(q1.x, q1.y, acc11, acc12)
            PAIR(q1.z, q1.w, acc11, acc12)
        }
#undef PAIR
        pb ^= 1;   // next visit writes the other buffer (no trailing sync)
    }

    red[wrp][0][lane]      = acc01;
    red[wrp][0][lane + 32] = acc02;
    red[wrp][1][lane]      = acc11;
    red[wrp][1][lane + 32] = acc12;
    __syncthreads();

    const int tid = threadIdx.x;
    if (tid < 2 * NBASIS) {
        const int r = tid >> 6;          // row within pair
        const int b = tid & 63;          // basis
        float s = 0.0f;
        #pragma unroll
        for (int w = 0; w < WPB; ++w) s += red[w][r][b];
        out[(i0 + r) * NBASIS + b] = s;
    }
}

extern "C" void kernel_launch(void* const* d_in, const int* in_sizes, int n_in,
                              void* d_out, int out_size) {
    const float* f      = (const float*)d_in[0];
    const float* coords = (const float*)d_in[1];
    const float* means  = (const float*)d_in[2];
    const float* beta   = (const float*)d_in[3];
    float* out          = (float*)d_out;

    const int N = in_sizes[0];   // 2048

    wgp_main_kernel<<<N / 2, WPB * 32>>>(f, coords, means, beta, out, N);
}

// round 10
// speedup vs baseline: 1.0737x; 1.0737x over previous
#include <cuda_runtime.h>
#include <math.h>

// WeightedGaussianPool: O[i,b] = sum_j cos(pi/2*d_ij)*step(1-d_ij)*f_j
//                                      * exp(-beta*(d_ij-means[b])^2)
// N=2048, B=64, beta=4096, means=linspace(0,1,64).
//
// R10 = R8 (best: 23.0us) + latency hiding in the consumer:
//  - software-pipelined LDS.128: prefetch pair-quad k+4 while computing k
//    (pair buffer sized so over-read is always in-bounds; values unused).
//  - 4 accumulators, alternating per pair: halves the predicated-FFMA RAW
//    dependency chain depth.
// Structure unchanged: block == row i (grid 2048, 128 thr), 64-wide j-chunks,
// ballot-compacted ping-pong pair list (one __syncwarp/visit), single
// predicate-routed EX2 per pair, block smem reduction, plain STG.

#define CUTOFF   5.0f
#define PI_HALF  1.5707963267948966f
#define NBASIS   64
#define WPB      4

__device__ __forceinline__ float ex2_fast(float x) {
    float r;
    asm("ex2.approx.ftz.f32 %0, %1;" : "=f"(r) : "f"(x));
    return r;
}
__device__ __forceinline__ float sqrt_fast(float x) {
    float r;
    asm("sqrt.approx.ftz.f32 %0, %1;" : "=f"(r) : "f"(x));
    return r;
}

__global__ __launch_bounds__(WPB * 32, 16)
void wgp_main_kernel(const float* __restrict__ f,
                     const float* __restrict__ coords,
                     const float* __restrict__ means,
                     const float* __restrict__ beta_p,
                     float* __restrict__ out,
                     int N) {
    // ping-pong pair list: 64 pairs + 3 pad + prefetch over-read headroom
    __shared__ __align__(16) float2 buf[WPB][2][72];
    __shared__ float red[WPB][NBASIS];

    const int lane = threadIdx.x & 31;
    const int wrp  = threadIdx.x >> 5;
    const int i    = blockIdx.x;                 // row

    const float beta = *beta_p;
    const float a    = sqrtf(beta * 1.4426950408889634f); // sqrt(beta*log2 e)
    const float aC   = a / CUTOFF;                         // raw-dist scale
    const float pC   = PI_HALF / CUTOFF;
    const float C2   = CUTOFF * CUTOFF;
    const float am1  = a * means[lane];
    const float am2  = a * means[lane + 32];
    const float D    = am2 - am1;                // warp-uniform
    const float midp = 0.5f * (am1 + am2);

    const float xi = coords[3 * i + 0];
    const float yi = coords[3 * i + 1];
    const float zi = coords[3 * i + 2];

    float acc1a = 0.0f, acc2a = 0.0f;
    float acc1b = 0.0f, acc2b = 0.0f;
    int pb = 0;

    const unsigned below = (1u << lane) - 1u;
    const int nch64 = N >> 6;                    // 64-wide chunks

    for (int c = wrp; c < nch64; c += WPB) {
        const int j0 = (c << 6) + lane;
        const int j1 = j0 + 32;

        // ---- produce pair 0 ----
        float dpA = 0.0f, wA = 0.0f;
        bool actA;
        {
            const float dx = xi - coords[3 * j0 + 0];
            const float dy = yi - coords[3 * j0 + 1];
            const float dz = zi - coords[3 * j0 + 2];
            const float sq = fmaf(dx, dx, fmaf(dy, dy, dz * dz));
            actA = (sq <= C2);
            if (actA) {
                const float dr = sqrt_fast(sq);
                dpA = aC * dr;
                wA  = __cosf(pC * dr) * f[j0];
            }
        }
        // ---- produce pair 1 ----
        float dpB = 0.0f, wB = 0.0f;
        bool actB;
        {
            const float dx = xi - coords[3 * j1 + 0];
            const float dy = yi - coords[3 * j1 + 1];
            const float dz = zi - coords[3 * j1 + 2];
            const float sq = fmaf(dx, dx, fmaf(dy, dy, dz * dz));
            actB = (sq <= C2);
            if (actB) {
                const float dr = sqrt_fast(sq);
                dpB = aC * dr;
                wB  = __cosf(pC * dr) * f[j1];
            }
        }

        const unsigned bitsA = __ballot_sync(0xffffffffu, actA);
        const unsigned bitsB = __ballot_sync(0xffffffffu, actB);
        const int nA = __popc(bitsA);
        const int nact = nA + __popc(bitsB);
        if (!nact) continue;

        float2* bp = buf[wrp][pb];
        if (actA) bp[__popc(bitsA & below)]      = make_float2(dpA, wA);
        if (actB) bp[nA + __popc(bitsB & below)] = make_float2(dpB, wB);
        if (lane < 3) bp[nact + lane] = make_float2(1.0e4f, 0.0f);  // pad x4
        __syncwarp();

        const int n4 = (nact + 3) & ~3;

#define PAIR(dq, wq, A1, A2)                                      \
        {                                                         \
            const float t1 = (dq) - am1;                          \
            const bool  lo = (dq) < midp;                         \
            const float t  = lo ? t1 : (t1 - D);                  \
            const float e  = ex2_fast(-t * t);                    \
            if (lo) A1 = fmaf((wq), e, A1);                       \
            else    A2 = fmaf((wq), e, A2);                       \
        }

        // software-pipelined: prefetch k+4 quad while computing k
        float4 q0 = *(const float4*)&bp[0];
        float4 q1 = *(const float4*)&bp[2];
        for (int k = 0; k < n4; k += 4) {
            const float4 p0 = q0;
            const float4 p1 = q1;
            q0 = *(const float4*)&bp[k + 4];   // over-read is in-bounds, unused past end
            q1 = *(const float4*)&bp[k + 6];
            PAIR(p0.x, p0.y, acc1a, acc2a)
            PAIR(p0.z, p0.w, acc1b, acc2b)
            PAIR(p1.x, p1.y, acc1a, acc2a)
            PAIR(p1.z, p1.w, acc1b, acc2b)
        }
#undef PAIR
        pb ^= 1;   // next visit writes the other buffer (no trailing sync)
    }

    // block reduction across WPB partitions, one STG per element
    red[wrp][lane]      = acc1a + acc1b;
    red[wrp][lane + 32] = acc2a + acc2b;
    __syncthreads();

    const int tid = threadIdx.x;
    if (tid < NBASIS) {
        float s = 0.0f;
        #pragma unroll
        for (int r = 0; r < WPB; ++r) s += red[r][tid];
        out[i * NBASIS + tid] = s;
    }
}

extern "C" void kernel_launch(void* const* d_in, const int* in_sizes, int n_in,
                              void* d_out, int out_size) {
    const float* f      = (const float*)d_in[0];
    const float* coords = (const float*)d_in[1];
    const float* means  = (const float*)d_in[2];
    const float* beta   = (const float*)d_in[3];
    float* out          = (float*)d_out;

    const int N = in_sizes[0];   // 2048

    wgp_main_kernel<<<N, WPB * 32>>>(f, coords, means, beta, out, N);
}

// round 11
// speedup vs baseline: 1.1224x; 1.0454x over previous
#include <cuda_runtime.h>
#include <math.h>

// WeightedGaussianPool: O[i,b] = sum_j cos(pi/2*d_ij)*step(1-d_ij)*f_j
//                                      * exp(-beta*(d_ij-means[b])^2)
// N=2048, B=64, beta=4096, means=linspace(0,1,64).
//
// R11 = R10 consumer + deeper producer amortization:
//  - prep kernel packs (x,y,z,f) into float4 -> 1 LDG.128 per j.
//  - 128-wide j-chunks: 4 pairs/lane/visit, produced+compacted group-by-group
//    into ONE list -> one sync/pad/consumer-pass per visit (visits 8->4/warp).
//  - consumer: software-pipelined LDS.128, 4 accumulators, single
//    predicate-routed EX2 per pair (lane l owns bases l, l+32).
//  - block == row i (grid 2048, 128 thr), block smem reduction, plain STG.

#define CUTOFF   5.0f
#define PI_HALF  1.5707963267948966f
#define NBASIS   64
#define WPB      4
#define NMAX     4096

__device__ float4 g_pk[NMAX];

__global__ void wgp_prep_kernel(const float* __restrict__ f,
                                const float* __restrict__ coords, int N) {
    int i = blockIdx.x * blockDim.x + threadIdx.x;
    if (i < N)
        g_pk[i] = make_float4(coords[3 * i + 0], coords[3 * i + 1],
                              coords[3 * i + 2], f[i]);
}

__device__ __forceinline__ float ex2_fast(float x) {
    float r;
    asm("ex2.approx.ftz.f32 %0, %1;" : "=f"(r) : "f"(x));
    return r;
}
__device__ __forceinline__ float sqrt_fast(float x) {
    float r;
    asm("sqrt.approx.ftz.f32 %0, %1;" : "=f"(r) : "f"(x));
    return r;
}

__global__ __launch_bounds__(WPB * 32, 16)
void wgp_main_kernel(const float* __restrict__ means,
                     const float* __restrict__ beta_p,
                     float* __restrict__ out,
                     int N) {
    // ping-pong pair list: 128 pairs + 3 pad + prefetch over-read headroom
    __shared__ __align__(16) float2 buf[WPB][2][140];
    __shared__ float red[WPB][NBASIS];

    const int lane = threadIdx.x & 31;
    const int wrp  = threadIdx.x >> 5;
    const int i    = blockIdx.x;                 // row

    const float beta = *beta_p;
    const float a    = sqrtf(beta * 1.4426950408889634f); // sqrt(beta*log2 e)
    const float aC   = a / CUTOFF;                         // raw-dist scale
    const float pC   = PI_HALF / CUTOFF;
    const float C2   = CUTOFF * CUTOFF;
    const float am1  = a * means[lane];
    const float am2  = a * means[lane + 32];
    const float D    = am2 - am1;                // warp-uniform
    const float midp = 0.5f * (am1 + am2);

    const float4 pi4 = g_pk[i];
    const float xi = pi4.x, yi = pi4.y, zi = pi4.z;

    float acc1a = 0.0f, acc2a = 0.0f;
    float acc1b = 0.0f, acc2b = 0.0f;
    int pb = 0;

    const unsigned below = (1u << lane) - 1u;
    const int nch128 = (N + 127) >> 7;           // 128-wide chunks

    for (int c = wrp; c < nch128; c += WPB) {
        float2* bp = buf[wrp][pb];
        int base = 0;

        #pragma unroll
        for (int g = 0; g < 4; ++g) {
            const int j = (c << 7) + (g << 5) + lane;
            const float4 p = g_pk[j];
            const float dx = xi - p.x;
            const float dy = yi - p.y;
            const float dz = zi - p.z;
            const float sq = fmaf(dx, dx, fmaf(dy, dy, dz * dz));
            const bool act = (sq <= C2) && (j < N);
            float dp = 0.0f, w = 0.0f;
            if (act) {
                const float dr = sqrt_fast(sq);
                dp = aC * dr;
                w  = __cosf(pC * dr) * p.w;
            }
            const unsigned b = __ballot_sync(0xffffffffu, act);
            if (act) bp[base + __popc(b & below)] = make_float2(dp, w);
            base += __popc(b);
        }

        const int nact = base;
        if (!nact) continue;

        if (lane < 3) bp[nact + lane] = make_float2(1.0e4f, 0.0f);  // pad x4
        __syncwarp();

        const int n4 = (nact + 3) & ~3;

#define PAIR(dq, wq, A1, A2)                                      \
        {                                                         \
            const float t1 = (dq) - am1;                          \
            const bool  lo = (dq) < midp;                         \
            const float t  = lo ? t1 : (t1 - D);                  \
            const float e  = ex2_fast(-t * t);                    \
            if (lo) A1 = fmaf((wq), e, A1);                       \
            else    A2 = fmaf((wq), e, A2);                       \
        }

        // software-pipelined: prefetch quad k+4 while computing k
        float4 q0 = *(const float4*)&bp[0];
        float4 q1 = *(const float4*)&bp[2];
        for (int k = 0; k < n4; k += 4) {
            const float4 p0 = q0;
            const float4 p1 = q1;
            q0 = *(const float4*)&bp[k + 4];   // over-read in-bounds, unused past end
            q1 = *(const float4*)&bp[k + 6];
            PAIR(p0.x, p0.y, acc1a, acc2a)
            PAIR(p0.z, p0.w, acc1b, acc2b)
            PAIR(p1.x, p1.y, acc1a, acc2a)
            PAIR(p1.z, p1.w, acc1b, acc2b)
        }
#undef PAIR
        pb ^= 1;   // next visit writes the other buffer (no trailing sync)
    }

    // block reduction across WPB partitions, one STG per element
    red[wrp][lane]      = acc1a + acc1b;
    red[wrp][lane + 32] = acc2a + acc2b;
    __syncthreads();

    const int tid = threadIdx.x;
    if (tid < NBASIS) {
        float s = 0.0f;
        #pragma unroll
        for (int r = 0; r < WPB; ++r) s += red[r][tid];
        out[i * NBASIS + tid] = s;
    }
}

extern "C" void kernel_launch(void* const* d_in, const int* in_sizes, int n_in,
                              void* d_out, int out_size) {
    const float* f      = (const float*)d_in[0];
    const float* coords = (const float*)d_in[1];
    const float* means  = (const float*)d_in[2];
    const float* beta   = (const float*)d_in[3];
    float* out          = (float*)d_out;

    const int N = in_sizes[0];   // 2048

    {
        int threads = 256;
        int blocks  = (N + threads - 1) / threads;
        wgp_prep_kernel<<<blocks, threads>>>(f, coords, N);
    }
    wgp_main_kernel<<<N, WPB * 32>>>(means, beta, out, N);
}